// round 2
// baseline (speedup 1.0000x reference)
#include <cuda_runtime.h>
#include <cuda_bf16.h>

#define B_ROWS 32768
#define FEAT_D 2048
#define NBLK   512
#define RPB    (B_ROWS / NBLK)   // 64 rows per block

// Scratch (device globals; no allocation allowed)
__device__ float  g_s[3][FEAT_D];   // per-class column sums of feat
__device__ double g_Q;              // sum of ||feat_b||^2
__device__ int    g_cnt[3];         // per-class row counts
__device__ int    g_stride;         // 1 if labels are int32, 2 if int64 (low word)

// Detect label dtype: int64 labels in {0,1,2} have all-zero odd int32 words.
__global__ void detect_k(const int* __restrict__ label32) {
    int nz = 0;
#pragma unroll
    for (int i = 0; i < 64; ++i) nz |= label32[2 * i + 1];
    g_stride = (nz == 0) ? 2 : 1;
}

__global__ void zero_k() {
    int i = blockIdx.x * blockDim.x + threadIdx.x;
    if (i < 3 * FEAT_D) ((float*)g_s)[i] = 0.0f;
    if (i == 0) { g_Q = 0.0; g_cnt[0] = 0; g_cnt[1] = 0; g_cnt[2] = 0; }
}

__global__ void __launch_bounds__(256, 4)
accum_k(const float* __restrict__ feat, const int* __restrict__ label32) {
    const int tid = threadIdx.x;
    const int stride = g_stride;

    // Thread covers float4 columns tid and tid+256 (block spans all 2048 cols)
    float4 A0 = {0,0,0,0}, B0 = {0,0,0,0};
    float4 A1 = {0,0,0,0}, B1 = {0,0,0,0};
    float4 A2 = {0,0,0,0}, B2 = {0,0,0,0};
    float  q  = 0.0f;
    int    c0 = 0, c1 = 0, c2 = 0;

    const int r0 = blockIdx.x * RPB;

#pragma unroll 4
    for (int r = r0; r < r0 + RPB; ++r) {
        const float4* fr = reinterpret_cast<const float4*>(feat) + (size_t)r * (FEAT_D / 4);
        float4 a = __ldg(fr + tid);
        float4 b = __ldg(fr + tid + 256);
        int l = label32[(size_t)stride * r];   // broadcast load, uniform across block

        q += a.x*a.x + a.y*a.y + a.z*a.z + a.w*a.w;
        q += b.x*b.x + b.y*b.y + b.z*b.z + b.w*b.w;

        if (l == 0) {
            c0++;
            A0.x += a.x; A0.y += a.y; A0.z += a.z; A0.w += a.w;
            B0.x += b.x; B0.y += b.y; B0.z += b.z; B0.w += b.w;
        } else if (l == 1) {
            c1++;
            A1.x += a.x; A1.y += a.y; A1.z += a.z; A1.w += a.w;
            B1.x += b.x; B1.y += b.y; B1.z += b.z; B1.w += b.w;
        } else {
            c2++;
            A2.x += a.x; A2.y += a.y; A2.z += a.z; A2.w += a.w;
            B2.x += b.x; B2.y += b.y; B2.z += b.z; B2.w += b.w;
        }
    }

    // Column-sum atomics: distinct address per (class, col); 512 colliders each
    const int cA = 4 * tid;
    const int cB = 4 * (tid + 256);
    atomicAdd(&g_s[0][cA+0], A0.x); atomicAdd(&g_s[0][cA+1], A0.y);
    atomicAdd(&g_s[0][cA+2], A0.z); atomicAdd(&g_s[0][cA+3], A0.w);
    atomicAdd(&g_s[0][cB+0], B0.x); atomicAdd(&g_s[0][cB+1], B0.y);
    atomicAdd(&g_s[0][cB+2], B0.z); atomicAdd(&g_s[0][cB+3], B0.w);

    atomicAdd(&g_s[1][cA+0], A1.x); atomicAdd(&g_s[1][cA+1], A1.y);
    atomicAdd(&g_s[1][cA+2], A1.z); atomicAdd(&g_s[1][cA+3], A1.w);
    atomicAdd(&g_s[1][cB+0], B1.x); atomicAdd(&g_s[1][cB+1], B1.y);
    atomicAdd(&g_s[1][cB+2], B1.z); atomicAdd(&g_s[1][cB+3], B1.w);

    atomicAdd(&g_s[2][cA+0], A2.x); atomicAdd(&g_s[2][cA+1], A2.y);
    atomicAdd(&g_s[2][cA+2], A2.z); atomicAdd(&g_s[2][cA+3], A2.w);
    atomicAdd(&g_s[2][cB+0], B2.x); atomicAdd(&g_s[2][cB+1], B2.y);
    atomicAdd(&g_s[2][cB+2], B2.z); atomicAdd(&g_s[2][cB+3], B2.w);

    // Counts: one thread per block, 3 int atomics
    if (tid == 0) {
        atomicAdd(&g_cnt[0], c0);
        atomicAdd(&g_cnt[1], c1);
        atomicAdd(&g_cnt[2], c2);
    }

    // Reduce q across block -> one double atomic per block
    __shared__ float warpq[8];
#pragma unroll
    for (int off = 16; off > 0; off >>= 1)
        q += __shfl_xor_sync(0xFFFFFFFFu, q, off);
    if ((tid & 31) == 0) warpq[tid >> 5] = q;
    __syncthreads();
    if (tid == 0) {
        float s = 0.0f;
#pragma unroll
        for (int w = 0; w < 8; ++w) s += warpq[w];
        atomicAdd(&g_Q, (double)s);
    }
}

__global__ void __launch_bounds__(256)
finalize_k(const float* __restrict__ centers, float* __restrict__ out) {
    const int tid = threadIdx.x;
    __shared__ double sbuf[256];

    double n0 = 0, n1 = 0, n2 = 0;            // ||c_j||^2
    double x0 = 0, x1 = 0, x2 = 0;            // s_j . c_j
    double ax = 0;                            // (s0+s1+s2) . (c0+c1+c2)

    for (int c = tid; c < FEAT_D; c += 256) {
        double c0 = centers[c], c1 = centers[FEAT_D + c], c2 = centers[2*FEAT_D + c];
        double s0 = g_s[0][c],  s1 = g_s[1][c],  s2 = g_s[2][c];
        n0 += c0*c0; n1 += c1*c1; n2 += c2*c2;
        x0 += s0*c0; x1 += s1*c1; x2 += s2*c2;
        ax += (s0+s1+s2) * (c0+c1+c2);
    }

    // generic block reduction for each scalar
    double vals[7] = {n0, n1, n2, x0, x1, x2, ax};
#pragma unroll
    for (int k = 0; k < 7; ++k) {
        sbuf[tid] = vals[k];
        __syncthreads();
        for (int s = 128; s > 0; s >>= 1) {
            if (tid < s) sbuf[tid] += sbuf[tid + s];
            __syncthreads();
        }
        vals[k] = sbuf[0];
        __syncthreads();
    }

    if (tid == 0) {
        double N0 = vals[0], N1 = vals[1], N2 = vals[2];
        double X0 = vals[3], X1 = vals[4], X2 = vals[5];
        double AX = vals[6];
        double C0 = (double)g_cnt[0], C1 = (double)g_cnt[1], C2 = (double)g_cnt[2];
        double Q  = g_Q;

        double S_main = Q - 2.0*(X0 + X1 + X2) + (C0*N0 + C1*N1 + C2*N2);
        double S_all  = 3.0*Q - 2.0*AX + (double)B_ROWS * (N0 + N1 + N2);
        double disto  = S_all - S_main;
        double loss   = S_main * (1.0 + 1.0 / disto) / 2.0 / (double)B_ROWS;
        out[0] = (float)loss;
    }
}

extern "C" void kernel_launch(void* const* d_in, const int* in_sizes, int n_in,
                              void* d_out, int out_size) {
    const float* feat    = (const float*)d_in[0];
    const int*   label32 = (const int*)d_in[1];
    const float* centers = (const float*)d_in[2];
    float*       out     = (float*)d_out;

    detect_k<<<1, 1>>>(label32);
    zero_k<<<(3 * FEAT_D + 255) / 256, 256>>>();
    accum_k<<<NBLK, 256>>>(feat, label32);
    finalize_k<<<1, 256>>>(centers, out);
}

// round 3
// speedup vs baseline: 1.9925x; 1.9925x over previous
#include <cuda_runtime.h>
#include <cuda_bf16.h>

#define B_ROWS 32768
#define FEAT_D 2048
#define NBLK   512
#define RPB    (B_ROWS / NBLK)   // 64 rows per block

// Global scalar accumulators (no allocation allowed)
__device__ double g_X;      // sum_j s_j . c_j
__device__ double g_AX;     // sum_cols T * (c0+c1+c2)
__device__ double g_Q;      // sum ||feat||^2
__device__ int    g_cnt0, g_cnt1;
__device__ int    g_ticket;
__device__ int    g_stride; // 1 = int32 labels, 2 = int64 (read low word)

__global__ void init_k(const int* __restrict__ label32) {
    if (threadIdx.x == 0) {
        g_X = 0.0; g_AX = 0.0; g_Q = 0.0;
        g_cnt0 = 0; g_cnt1 = 0; g_ticket = 0;
        // int64 labels in {0,1,2}: odd int32 words all zero. For int32 labels
        // P(64 draws from {0,1,2} all land 0 at odd slots) ~ (1/3)^64 ~ 0.
        int nz = 0;
#pragma unroll
        for (int i = 0; i < 64; ++i) nz |= label32[2 * i + 1];
        g_stride = nz ? 1 : 2;
    }
}

__device__ __forceinline__ double blk_reduce(double v, double (*sred)[4], int slot,
                                             int tid) {
    // warp shuffle reduce
#pragma unroll
    for (int off = 16; off > 0; off >>= 1)
        v += __shfl_xor_sync(0xFFFFFFFFu, v, off);
    if ((tid & 31) == 0) sred[tid >> 5][slot] = v;
    __syncthreads();
    double r = 0.0;
    if (tid < 8) r = sred[tid][slot];
#pragma unroll
    for (int off = 4; off > 0; off >>= 1)
        r += __shfl_xor_sync(0xFFu, r, off);
    return r;  // valid in tid 0
}

__global__ void __launch_bounds__(256, 4)
accum_k(const float* __restrict__ feat, const int* __restrict__ label32,
        const float* __restrict__ centers, float* __restrict__ out) {
    __shared__ int    s_lab[RPB];
    __shared__ double s_red[8][4];
    __shared__ int    s_last;

    const int tid = threadIdx.x;
    const int r0  = blockIdx.x * RPB;

    if (tid < RPB) s_lab[tid] = label32[(size_t)g_stride * (r0 + tid)];
    __syncthreads();

    // Thread owns float4 columns tid and tid+256 (block spans all 2048 cols)
    float4 A0a = {0,0,0,0}, A0b = {0,0,0,0};   // class-0 partial column sums
    float4 A1a = {0,0,0,0}, A1b = {0,0,0,0};   // class-1
    float4 Ta  = {0,0,0,0}, Tb  = {0,0,0,0};   // total (class-2 = T - A0 - A1)
    float  qa = 0.0f, qb = 0.0f;

    const float4* fp = reinterpret_cast<const float4*>(feat)
                     + (size_t)r0 * (FEAT_D / 4) + tid;

#pragma unroll 2
    for (int i = 0; i < RPB; ++i, fp += FEAT_D / 4) {
        float4 a = fp[0];
        float4 b = fp[256];
        const int l = s_lab[i];
        const float m0 = (l == 0) ? 1.0f : 0.0f;
        const float m1 = (l == 1) ? 1.0f : 0.0f;

        qa += a.x*a.x + a.y*a.y + a.z*a.z + a.w*a.w;
        qb += b.x*b.x + b.y*b.y + b.z*b.z + b.w*b.w;

        Ta.x += a.x; Ta.y += a.y; Ta.z += a.z; Ta.w += a.w;
        Tb.x += b.x; Tb.y += b.y; Tb.z += b.z; Tb.w += b.w;

        A0a.x = fmaf(m0, a.x, A0a.x); A0a.y = fmaf(m0, a.y, A0a.y);
        A0a.z = fmaf(m0, a.z, A0a.z); A0a.w = fmaf(m0, a.w, A0a.w);
        A0b.x = fmaf(m0, b.x, A0b.x); A0b.y = fmaf(m0, b.y, A0b.y);
        A0b.z = fmaf(m0, b.z, A0b.z); A0b.w = fmaf(m0, b.w, A0b.w);

        A1a.x = fmaf(m1, a.x, A1a.x); A1a.y = fmaf(m1, a.y, A1a.y);
        A1a.z = fmaf(m1, a.z, A1a.z); A1a.w = fmaf(m1, a.w, A1a.w);
        A1b.x = fmaf(m1, b.x, A1b.x); A1b.y = fmaf(m1, b.y, A1b.y);
        A1b.z = fmaf(m1, b.z, A1b.z); A1b.w = fmaf(m1, b.w, A1b.w);
    }

    // ---- per-thread dot products with centers (fp32, double at reduction) ----
    const float4* c4 = reinterpret_cast<const float4*>(centers);
    const int cA = tid, cB = tid + 256;
    float4 C0a = c4[cA],        C0b = c4[cB];
    float4 C1a = c4[512  + cA], C1b = c4[512  + cB];
    float4 C2a = c4[1024 + cA], C2b = c4[1024 + cB];

    float x = 0.0f, ax = 0.0f;
    {
        // component-wise: x += A0*c0 + A1*c1 + (T-A0-A1)*c2 ; ax += T*(c0+c1+c2)
#define DOT1(AA0, AA1, TT, CC0, CC1, CC2, comp)                                  \
        {  float a2 = TT.comp - AA0.comp - AA1.comp;                             \
           x  = fmaf(AA0.comp, CC0.comp, x);                                     \
           x  = fmaf(AA1.comp, CC1.comp, x);                                     \
           x  = fmaf(a2,       CC2.comp, x);                                     \
           ax = fmaf(TT.comp, CC0.comp + CC1.comp + CC2.comp, ax); }
        DOT1(A0a, A1a, Ta, C0a, C1a, C2a, x) DOT1(A0a, A1a, Ta, C0a, C1a, C2a, y)
        DOT1(A0a, A1a, Ta, C0a, C1a, C2a, z) DOT1(A0a, A1a, Ta, C0a, C1a, C2a, w)
        DOT1(A0b, A1b, Tb, C0b, C1b, C2b, x) DOT1(A0b, A1b, Tb, C0b, C1b, C2b, y)
        DOT1(A0b, A1b, Tb, C0b, C1b, C2b, z) DOT1(A0b, A1b, Tb, C0b, C1b, C2b, w)
#undef DOT1
    }

    double xr  = blk_reduce((double)x,          s_red, 0, tid);
    __syncthreads();
    double axr = blk_reduce((double)ax,         s_red, 1, tid);
    __syncthreads();
    double qr  = blk_reduce((double)qa + (double)qb, s_red, 2, tid);

    if (tid == 0) {
        int c0 = 0, c1 = 0;
#pragma unroll
        for (int i = 0; i < RPB; ++i) {
            c0 += (s_lab[i] == 0);
            c1 += (s_lab[i] == 1);
        }
        atomicAdd(&g_cnt0, c0);
        atomicAdd(&g_cnt1, c1);
        atomicAdd(&g_X,  xr);
        atomicAdd(&g_AX, axr);
        atomicAdd(&g_Q,  qr);
        __threadfence();
        int t = atomicAdd(&g_ticket, 1);
        s_last = (t == NBLK - 1);
    }
    __syncthreads();
    if (!s_last) return;

    // ---------------- last block: finalize ----------------
    __threadfence();

    double n0 = 0, n1 = 0, n2 = 0;   // ||c_j||^2
#pragma unroll
    for (int c = tid; c < FEAT_D; c += 256) {
        float v0 = centers[c];
        float v1 = centers[FEAT_D + c];
        float v2 = centers[2 * FEAT_D + c];
        n0 += (double)(v0 * v0);
        n1 += (double)(v1 * v1);
        n2 += (double)(v2 * v2);
    }
    __syncthreads();   // s_red reuse
    double N0 = blk_reduce(n0, s_red, 0, tid);
    __syncthreads();
    double N1 = blk_reduce(n1, s_red, 1, tid);
    __syncthreads();
    double N2 = blk_reduce(n2, s_red, 2, tid);

    if (tid == 0) {
        double X  = atomicAdd(&g_X,  0.0);
        double AX = atomicAdd(&g_AX, 0.0);
        double Q  = atomicAdd(&g_Q,  0.0);
        double C0 = (double)atomicAdd(&g_cnt0, 0);
        double C1 = (double)atomicAdd(&g_cnt1, 0);
        double C2 = (double)B_ROWS - C0 - C1;

        double S_main = Q - 2.0 * X + (C0 * N0 + C1 * N1 + C2 * N2);
        double S_all  = 3.0 * Q - 2.0 * AX + (double)B_ROWS * (N0 + N1 + N2);
        double disto  = S_all - S_main;
        double loss   = S_main * (1.0 + 1.0 / disto) / 2.0 / (double)B_ROWS;
        out[0] = (float)loss;
    }
}

extern "C" void kernel_launch(void* const* d_in, const int* in_sizes, int n_in,
                              void* d_out, int out_size) {
    const float* feat    = (const float*)d_in[0];
    const int*   label32 = (const int*)d_in[1];
    const float* centers = (const float*)d_in[2];
    float*       out     = (float*)d_out;

    init_k<<<1, 32>>>(label32);
    accum_k<<<NBLK, 256>>>(feat, label32, centers, out);
}